// round 15
// baseline (speedup 1.0000x reference)
#include <cuda_runtime.h>
#include <cuda.h>

// VolumeRotation: B=8, C=16, S=64 — round 14: TMA multicast + full occupancy.
// Cluster of 2 CTAs shares one 16^3 tile (rank = z half), 1024 threads/CTA
// (SPT=2, 32 warps/SM, regs capped at 64). One multicast tensor.4d per
// channel fills the 32x29x29f window (SW128, HW zero-fill) into BOTH CTAs'
// smem for one L2 read. Double buffer + per-step consumption handshake.
// Fallback: round-12 non-cluster TMA kernel (133us proven).

#define SB 64
#define CB 16
#define S3 (SB*SB*SB)
#define TT 16
#define WWN 29
#define NROWS (WWN*WWN)           // 841
#define WIN_BYTES (NROWS*128)     // 107648
#define WIN_STRIDE 108544         // 1024B multiple
#define SMEM_BYTES (2*WIN_STRIDE + 1024)

#define CNTHR 1024
#define CSPT 2
#define FNTHR 1024
#define FSPT 4

__device__ __forceinline__ void sample_pos(
    float r00, float r01, float r02,
    float r10, float r11, float r12,
    float r20, float r21, float r22,
    int x, int y, int z,
    float& fx, float& fy, float& fz)
{
    const float sc = 2.0f / 63.0f;
    float bx = fmaf((float)x, sc, -1.0f);
    float by = fmaf((float)y, sc, -1.0f);
    float bz = fmaf((float)z, sc, -1.0f);
    float gx = fmaf(r00, bx, fmaf(r10, by, r20 * bz));
    float gy = fmaf(r01, bx, fmaf(r11, by, r21 * bz));
    float gz = fmaf(r02, bx, fmaf(r12, by, r22 * bz));
    fx = fmaf(gx, 32.0f, 31.5f);
    fy = fmaf(gy, 32.0f, 31.5f);
    fz = fmaf(gz, 32.0f, 31.5f);
}

#define MBAR_WAIT(bar, par) do {                                              \
    unsigned _done;                                                           \
    asm volatile("{\n\t.reg .pred p;\n\t"                                     \
        "mbarrier.try_wait.parity.acquire.cta.shared::cta.b64 p, [%1], %2;\n\t"\
        "selp.b32 %0, 1, 0, p;\n\t}"                                          \
        : "=r"(_done) : "r"(bar), "r"(par) : "memory");                       \
    if (!_done) {                                                             \
        asm volatile("{\n\t.reg .pred P1;\n\t"                                \
            "WL_%=:\n\t"                                                      \
            "mbarrier.try_wait.parity.acquire.cta.shared::cta.b64 P1, [%0], %1, 0x989680;\n\t" \
            "@P1 bra.uni WD_%=;\n\t"                                          \
            "bra.uni WL_%=;\n\t"                                              \
            "WD_%=:\n\t}"                                                     \
            :: "r"(bar), "r"(par) : "memory");                                \
    }                                                                         \
} while (0)

#define CLUSTER_SYNC() do {                                                   \
    asm volatile("barrier.cluster.arrive.aligned;" ::: "memory");             \
    asm volatile("barrier.cluster.wait.aligned;" ::: "memory");               \
} while (0)

// ===================== cluster multicast kernel ============================

__global__ __launch_bounds__(CNTHR, 1) __cluster_dims__(2, 1, 1)
void volrot_mc(const __grid_constant__ CUtensorMap tmap,
               const float* __restrict__ rot,
               float* __restrict__ out)
{
    extern __shared__ float smemf[];
    __shared__ __align__(16) unsigned long long full_bar[2];
    __shared__ __align__(16) unsigned long long ready_bar;

    int tid = threadIdx.x;
    unsigned rank;
    asm("mov.u32 %0, %%cluster_ctarank;" : "=r"(rank));

    int cl = blockIdx.x >> 1;         // cluster id = tile id
    int b = cl >> 6;
    int t = cl & 63;
    int oz = (t >> 4) * TT;
    int oy = ((t >> 2) & 3) * TT;
    int ox = (t & 3) * TT;

    unsigned su_raw = (unsigned)__cvta_generic_to_shared(smemf);
    unsigned su = (su_raw + 1023u) & ~1023u;
    const char* wbase = (const char*)smemf + (su - su_raw);
    unsigned fb0 = (unsigned)__cvta_generic_to_shared(&full_bar[0]);
    unsigned rb  = (unsigned)__cvta_generic_to_shared(&ready_bar);

    const float* R = rot + b * 9;
    float r00 = __ldg(R+0), r01 = __ldg(R+1), r02 = __ldg(R+2);
    float r10 = __ldg(R+3), r11 = __ldg(R+4), r12 = __ldg(R+5);
    float r20 = __ldg(R+6), r21 = __ldg(R+7), r22 = __ldg(R+8);

    // window base over the FULL tile (identical in both ranks)
    float mnx = 1e30f, mny = 1e30f, mnz = 1e30f;
    #pragma unroll
    for (int k = 0; k < 8; k++) {
        int cx = ox + ((k & 1) ? TT - 1 : 0);
        int cy = oy + ((k & 2) ? TT - 1 : 0);
        int cz = oz + ((k & 4) ? TT - 1 : 0);
        float fx, fy, fz;
        sample_pos(r00,r01,r02,r10,r11,r12,r20,r21,r22, cx, cy, cz, fx, fy, fz);
        mnx = fminf(mnx, fx); mny = fminf(mny, fy); mnz = fminf(mnz, fz);
    }
    int bax = ((int)floorf(mnx)) & ~3;
    int bay = (int)floorf(mny);
    int baz = (int)floorf(mnz);

    // per-sample channel-invariant state; rank owns z-half (lz = rank*8 + ..)
    unsigned pk[CSPT];
    float ex0[CSPT], ex1[CSPT], wp0[CSPT], wp1[CSPT], wp2[CSPT], wp3[CSPT];
    unsigned obyte0 = 0;

    #pragma unroll
    for (int s = 0; s < CSPT; s++) {
        int v = (int)(tid + rank * 2048 + s * CNTHR);   // 0..4095
        int lx = v & 15, ly = (v >> 4) & 15, lz = v >> 8;
        int x = ox + lx, y = oy + ly, z = oz + lz;
        float fx, fy, fz;
        sample_pos(r00,r01,r02,r10,r11,r12,r20,r21,r22, x, y, z, fx, fy, fz);
        float x0f = floorf(fx), y0f = floorf(fy), z0f = floorf(fz);
        float tx = fx - x0f, ty = fy - y0f, tz = fz - z0f;
        int x0 = (int)x0f, y0 = (int)y0f, z0 = (int)z0f;

        ex0[s] = 1.0f - tx;  ex1[s] = tx;
        wp0[s] = (1.0f - ty) * (1.0f - tz);
        wp1[s] = ty * (1.0f - tz);
        wp2[s] = (1.0f - ty) * tz;
        wp3[s] = ty * tz;

        int wx0 = min(max(x0 - bax, 0), 30);
        int wy0 = min(max(y0 - bay, 0), WWN - 2);
        int wz0 = min(max(z0 - baz, 0), WWN - 2);
        unsigned rowid = (unsigned)(wz0 * WWN + wy0);
        unsigned ca0 = (unsigned)((((wx0    ) >> 2) << 4) | (((wx0    ) & 3) << 2));
        unsigned ca1 = (unsigned)((((wx0 + 1) >> 2) << 4) | (((wx0 + 1) & 3) << 2));
        pk[s] = rowid | (ca0 << 10) | (ca1 << 18);
        if (s == 0) obyte0 = (unsigned)((((z * SB) + y) * SB + x) * 4);
    }

    if (tid == 0) {
        asm volatile("mbarrier.init.shared.b64 [%0], 1;" :: "r"(fb0)     : "memory");
        asm volatile("mbarrier.init.shared.b64 [%0], 1;" :: "r"(fb0 + 8) : "memory");
        asm volatile("mbarrier.init.shared.b64 [%0], 2;" :: "r"(rb)      : "memory");
        // arm both local full barriers for the prologue fills
        asm volatile("mbarrier.arrive.expect_tx.shared.b64 _, [%0], %1;"
            :: "r"(fb0), "r"((unsigned)WIN_BYTES) : "memory");
        asm volatile("mbarrier.arrive.expect_tx.shared.b64 _, [%0], %1;"
            :: "r"(fb0 + 8), "r"((unsigned)WIN_BYTES) : "memory");
    }
    __syncthreads();
    CLUSTER_SYNC();                  // barriers armed in BOTH CTAs

    int wcoord = b * CB;
    if (rank == 0 && tid == 0) {
        #pragma unroll
        for (int c = 0; c < 2; c++) {
            asm volatile(
                "cp.async.bulk.tensor.4d.shared::cluster.global.tile"
                ".mbarrier::complete_tx::bytes.multicast::cluster "
                "[%0], [%1, {%2, %3, %4, %5}], [%6], %7;"
                :: "r"(su + (unsigned)c * (unsigned)WIN_STRIDE), "l"(&tmap),
                   "r"(bax), "r"(bay), "r"(baz), "r"(wcoord + c),
                   "r"(fb0 + 8u * (unsigned)c), "h"((unsigned short)3)
                : "memory");
        }
    }

    char* dstb = (char*)out + (size_t)b * CB * S3 * 4;
    int rphase = 0;

    #pragma unroll 1
    for (int c = 0; c < CB; c++) {
        unsigned bar = fb0 + 8u * (unsigned)(c & 1);
        MBAR_WAIT(bar, (c >> 1) & 1);

        const char* wb = wbase + (unsigned)(c & 1) * (unsigned)WIN_STRIDE;
        char* dc = dstb + (size_t)c * S3 * 4 + obyte0;
        #pragma unroll
        for (int s = 0; s < CSPT; s++) {
            unsigned p = pk[s];
            unsigned rowid = p & 1023u;
            unsigned ca0 = (p >> 10) & 0xFFu;
            unsigned ca1 = (p >> 18) & 0xFFu;

            unsigned rk0 = rowid * 128 + ((rowid & 7) << 4);
            unsigned rr1 = rowid + 1;
            unsigned rk1 = rr1 * 128 + ((rr1 & 7) << 4);
            unsigned rr2 = rowid + WWN;
            unsigned rk2 = rr2 * 128 + ((rr2 & 7) << 4);
            unsigned rr3 = rowid + WWN + 1;
            unsigned rk3 = rr3 * 128 + ((rr3 & 7) << 4);

            float v00 = *(const float*)(wb + (rk0 ^ ca0));
            float v01 = *(const float*)(wb + (rk0 ^ ca1));
            float v10 = *(const float*)(wb + (rk1 ^ ca0));
            float v11 = *(const float*)(wb + (rk1 ^ ca1));
            float v20 = *(const float*)(wb + (rk2 ^ ca0));
            float v21 = *(const float*)(wb + (rk2 ^ ca1));
            float v30 = *(const float*)(wb + (rk3 ^ ca0));
            float v31 = *(const float*)(wb + (rk3 ^ ca1));

            float s0 = fmaf(ex0[s], v00, ex1[s] * v01);
            float s1 = fmaf(ex0[s], v10, ex1[s] * v11);
            float s2 = fmaf(ex0[s], v20, ex1[s] * v21);
            float s3 = fmaf(ex0[s], v30, ex1[s] * v31);
            float acc = wp0[s] * s0;
            acc = fmaf(wp1[s], s1, acc);
            acc = fmaf(wp2[s], s2, acc);
            acc = fmaf(wp3[s], s3, acc);
            // v += 1024 per s => lz += 4 => +65536 bytes
            *(float*)(dc + (unsigned)(s * 65536)) = acc;
        }

        __syncthreads();   // CTA done reading buffer (c&1)

        if (c + 2 < CB) {
            if (tid == 0) {
                // re-arm local full barrier, then signal consumption to leader
                asm volatile("mbarrier.arrive.expect_tx.shared.b64 _, [%0], %1;"
                    :: "r"(bar), "r"((unsigned)WIN_BYTES) : "memory");
                if (rank == 0) {
                    asm volatile("mbarrier.arrive.shared.b64 _, [%0];"
                        :: "r"(rb) : "memory");
                } else {
                    asm volatile("{\n\t.reg .b32 ra;\n\t"
                        "mapa.shared::cluster.u32 ra, %0, 0;\n\t"
                        "mbarrier.arrive.shared::cluster.b64 _, [ra];\n\t}"
                        :: "r"(rb) : "memory");
                }
            }
            if (rank == 0 && tid == 0) {
                MBAR_WAIT(rb, rphase & 1);
                rphase++;
                asm volatile(
                    "cp.async.bulk.tensor.4d.shared::cluster.global.tile"
                    ".mbarrier::complete_tx::bytes.multicast::cluster "
                    "[%0], [%1, {%2, %3, %4, %5}], [%6], %7;"
                    :: "r"(su + (unsigned)(c & 1) * (unsigned)WIN_STRIDE),
                       "l"(&tmap),
                       "r"(bax), "r"(bay), "r"(baz), "r"(wcoord + c + 2),
                       "r"(bar), "h"((unsigned short)3)
                    : "memory");
            }
        }
    }

    CLUSTER_SYNC();   // no CTA exits while peer-targeted multicast may be live
}

// ================ fallback: round-12 non-cluster TMA kernel ================

__global__ __launch_bounds__(FNTHR, 1)
void volrot_tma(const __grid_constant__ CUtensorMap tmap,
                const float* __restrict__ rot,
                float* __restrict__ out)
{
    extern __shared__ float smemf[];
    __shared__ __align__(16) unsigned long long mbar[2];

    int tid = threadIdx.x;
    int blk = blockIdx.x;
    int b = blk >> 6;
    int t = blk & 63;
    int oz = (t >> 4) * TT;
    int oy = ((t >> 2) & 3) * TT;
    int ox = (t & 3) * TT;

    unsigned su_raw = (unsigned)__cvta_generic_to_shared(smemf);
    unsigned su = (su_raw + 1023u) & ~1023u;
    const char* wbase = (const char*)smemf + (su - su_raw);
    unsigned bar0 = (unsigned)__cvta_generic_to_shared(&mbar[0]);

    const float* R = rot + b * 9;
    float r00 = __ldg(R+0), r01 = __ldg(R+1), r02 = __ldg(R+2);
    float r10 = __ldg(R+3), r11 = __ldg(R+4), r12 = __ldg(R+5);
    float r20 = __ldg(R+6), r21 = __ldg(R+7), r22 = __ldg(R+8);

    float mnx = 1e30f, mny = 1e30f, mnz = 1e30f;
    #pragma unroll
    for (int k = 0; k < 8; k++) {
        int cx = ox + ((k & 1) ? TT - 1 : 0);
        int cy = oy + ((k & 2) ? TT - 1 : 0);
        int cz = oz + ((k & 4) ? TT - 1 : 0);
        float fx, fy, fz;
        sample_pos(r00,r01,r02,r10,r11,r12,r20,r21,r22, cx, cy, cz, fx, fy, fz);
        mnx = fminf(mnx, fx); mny = fminf(mny, fy); mnz = fminf(mnz, fz);
    }
    int bax = ((int)floorf(mnx)) & ~3;
    int bay = (int)floorf(mny);
    int baz = (int)floorf(mnz);

    unsigned pk[FSPT];
    float ex0[FSPT], ex1[FSPT], wp0[FSPT], wp1[FSPT], wp2[FSPT], wp3[FSPT];
    unsigned obyte0 = 0;

    #pragma unroll
    for (int s = 0; s < FSPT; s++) {
        int v = tid + s * FNTHR;
        int lx = v & 15, ly = (v >> 4) & 15, lz = v >> 8;
        int x = ox + lx, y = oy + ly, z = oz + lz;
        float fx, fy, fz;
        sample_pos(r00,r01,r02,r10,r11,r12,r20,r21,r22, x, y, z, fx, fy, fz);
        float x0f = floorf(fx), y0f = floorf(fy), z0f = floorf(fz);
        float tx = fx - x0f, ty = fy - y0f, tz = fz - z0f;
        int x0 = (int)x0f, y0 = (int)y0f, z0 = (int)z0f;

        ex0[s] = 1.0f - tx;  ex1[s] = tx;
        wp0[s] = (1.0f - ty) * (1.0f - tz);
        wp1[s] = ty * (1.0f - tz);
        wp2[s] = (1.0f - ty) * tz;
        wp3[s] = ty * tz;

        int wx0 = min(max(x0 - bax, 0), 30);
        int wy0 = min(max(y0 - bay, 0), WWN - 2);
        int wz0 = min(max(z0 - baz, 0), WWN - 2);
        unsigned rowid = (unsigned)(wz0 * WWN + wy0);
        unsigned ca0 = (unsigned)((((wx0    ) >> 2) << 4) | (((wx0    ) & 3) << 2));
        unsigned ca1 = (unsigned)((((wx0 + 1) >> 2) << 4) | (((wx0 + 1) & 3) << 2));
        pk[s] = rowid | (ca0 << 10) | (ca1 << 18);
        if (s == 0) obyte0 = (unsigned)((((z * SB) + y) * SB + x) * 4);
    }

    if (tid == 0) {
        asm volatile("mbarrier.init.shared.b64 [%0], 1;" :: "r"(bar0)     : "memory");
        asm volatile("mbarrier.init.shared.b64 [%0], 1;" :: "r"(bar0 + 8) : "memory");
    }
    __syncthreads();

    int wcoord = b * CB;
    if (tid == 0) {
        #pragma unroll
        for (int c = 0; c < 2; c++) {
            unsigned bar = bar0 + 8u * (unsigned)c;
            asm volatile("mbarrier.arrive.expect_tx.shared.b64 _, [%0], %1;"
                :: "r"(bar), "r"((unsigned)WIN_BYTES) : "memory");
            asm volatile(
                "cp.async.bulk.tensor.4d.shared::cta.global.tile.mbarrier::complete_tx::bytes "
                "[%0], [%1, {%2, %3, %4, %5}], [%6];"
                :: "r"(su + (unsigned)c * (unsigned)WIN_STRIDE), "l"(&tmap),
                   "r"(bax), "r"(bay), "r"(baz), "r"(wcoord + c), "r"(bar)
                : "memory");
        }
    }

    char* dstb = (char*)out + (size_t)b * CB * S3 * 4;

    #pragma unroll 1
    for (int c = 0; c < CB; c++) {
        unsigned bar = bar0 + 8u * (unsigned)(c & 1);
        MBAR_WAIT(bar, (c >> 1) & 1);

        const char* wb = wbase + (unsigned)(c & 1) * (unsigned)WIN_STRIDE;
        char* dc = dstb + (size_t)c * S3 * 4 + obyte0;
        #pragma unroll
        for (int s = 0; s < FSPT; s++) {
            unsigned p = pk[s];
            unsigned rowid = p & 1023u;
            unsigned ca0 = (p >> 10) & 0xFFu;
            unsigned ca1 = (p >> 18) & 0xFFu;

            unsigned rk0 = rowid * 128 + ((rowid & 7) << 4);
            unsigned rr1 = rowid + 1;
            unsigned rk1 = rr1 * 128 + ((rr1 & 7) << 4);
            unsigned rr2 = rowid + WWN;
            unsigned rk2 = rr2 * 128 + ((rr2 & 7) << 4);
            unsigned rr3 = rowid + WWN + 1;
            unsigned rk3 = rr3 * 128 + ((rr3 & 7) << 4);

            float v00 = *(const float*)(wb + (rk0 ^ ca0));
            float v01 = *(const float*)(wb + (rk0 ^ ca1));
            float v10 = *(const float*)(wb + (rk1 ^ ca0));
            float v11 = *(const float*)(wb + (rk1 ^ ca1));
            float v20 = *(const float*)(wb + (rk2 ^ ca0));
            float v21 = *(const float*)(wb + (rk2 ^ ca1));
            float v30 = *(const float*)(wb + (rk3 ^ ca0));
            float v31 = *(const float*)(wb + (rk3 ^ ca1));

            float s0 = fmaf(ex0[s], v00, ex1[s] * v01);
            float s1 = fmaf(ex0[s], v10, ex1[s] * v11);
            float s2 = fmaf(ex0[s], v20, ex1[s] * v21);
            float s3 = fmaf(ex0[s], v30, ex1[s] * v31);
            float acc = wp0[s] * s0;
            acc = fmaf(wp1[s], s1, acc);
            acc = fmaf(wp2[s], s2, acc);
            acc = fmaf(wp3[s], s3, acc);
            *(float*)(dc + (unsigned)(s * 65536)) = acc;
        }

        __syncthreads();
        if (c + 2 < CB && tid == 0) {
            asm volatile("mbarrier.arrive.expect_tx.shared.b64 _, [%0], %1;"
                :: "r"(bar), "r"((unsigned)WIN_BYTES) : "memory");
            asm volatile(
                "cp.async.bulk.tensor.4d.shared::cta.global.tile.mbarrier::complete_tx::bytes "
                "[%0], [%1, {%2, %3, %4, %5}], [%6];"
                :: "r"(su + (unsigned)(c & 1) * (unsigned)WIN_STRIDE), "l"(&tmap),
                   "r"(bax), "r"(bay), "r"(baz), "r"(wcoord + c + 2), "r"(bar)
                : "memory");
        }
    }
}

// ================================ host =====================================

extern "C" void kernel_launch(void* const* d_in, const int* in_sizes, int n_in,
                              void* d_out, int out_size)
{
    const float* vol = (const float*)d_in[0];
    const float* rot = (const float*)d_in[1];
    float* out = (float*)d_out;

    typedef CUresult (*EncodeFn)(
        CUtensorMap*, CUtensorMapDataType, cuuint32_t, void*,
        const cuuint64_t*, const cuuint64_t*, const cuuint32_t*,
        const cuuint32_t*, CUtensorMapInterleave, CUtensorMapSwizzle,
        CUtensorMapL2promotion, CUtensorMapFloatOOBfill);
    EncodeFn encode = nullptr;
#if CUDART_VERSION >= 12050
    cudaDriverEntryPointQueryResult qr;
    if (cudaGetDriverEntryPointByVersion("cuTensorMapEncodeTiled",
            (void**)&encode, 12000, cudaEnableDefault, &qr) != cudaSuccess ||
        qr != cudaDriverEntryPointSuccess)
        encode = nullptr;
#else
    if (cudaGetDriverEntryPoint("cuTensorMapEncodeTiled",
            (void**)&encode, cudaEnableDefault) != cudaSuccess)
        encode = nullptr;
#endif

    CUtensorMap tmap;
    __builtin_memset(&tmap, 0, sizeof(tmap));
    cuuint64_t dims[4]    = {64, 64, 64, 128};
    cuuint64_t strides[3] = {64ull * 4, 64ull * 64 * 4, 64ull * 64 * 64 * 4};
    cuuint32_t box[4]     = {32, WWN, WWN, 1};
    cuuint32_t est[4]     = {1, 1, 1, 1};
    encode(&tmap, CU_TENSOR_MAP_DATA_TYPE_FLOAT32, 4, (void*)vol,
           dims, strides, box, est,
           CU_TENSOR_MAP_INTERLEAVE_NONE, CU_TENSOR_MAP_SWIZZLE_128B,
           CU_TENSOR_MAP_L2_PROMOTION_L2_128B,
           CU_TENSOR_MAP_FLOAT_OOB_FILL_NONE);

    cudaFuncSetAttribute(volrot_mc,
                         cudaFuncAttributeMaxDynamicSharedMemorySize, SMEM_BYTES);
    cudaFuncSetAttribute(volrot_tma,
                         cudaFuncAttributeMaxDynamicSharedMemorySize, SMEM_BYTES);

    cudaLaunchConfig_t cfg = {};
    cfg.gridDim = dim3(8 * 64 * 2, 1, 1);
    cfg.blockDim = dim3(CNTHR, 1, 1);
    cfg.dynamicSmemBytes = SMEM_BYTES;
    cudaLaunchAttribute attrs[1];
    attrs[0].id = cudaLaunchAttributeClusterDimension;
    attrs[0].val.clusterDim = {2, 1, 1};
    cfg.attrs = attrs;
    cfg.numAttrs = 1;

    cudaError_t err = cudaLaunchKernelEx(&cfg, volrot_mc, tmap, rot, out);
    if (err != cudaSuccess) {
        cudaGetLastError();
        volrot_tma<<<8 * 64, FNTHR, SMEM_BYTES>>>(tmap, rot, out);
    }
}

// round 17
// speedup vs baseline: 1.2655x; 1.2655x over previous
#include <cuda_runtime.h>
#include <cuda.h>

// VolumeRotation: B=8, C=16, S=64 — round 16: TMA runtime-culled boxes,
// fail-closed. R12 single-CTA TMA pipeline + 25 pre-encoded tensor maps with
// box (32, WY, WZ), WY/WZ in {21,23,25,27,29}. Each block picks the smallest
// sufficient box (avg ~25 => ~26% less fill traffic / smem writes). If ANY
// encode fails, `culled=0` forces the 29x29 map everywhere so expect_tx bytes
// always match the map used (fixes the R15 potential mbarrier hang).

#define SB 64
#define CB 16
#define S3 (SB*SB*SB)
#define TT 16
#define NTHR 1024
#define SPT 4
#define WMAX 29
#define WIN_STRIDE 108544               // >= 29*29*128, 1024B multiple
#define SMEM_BYTES (2*WIN_STRIDE + 1024)

struct Maps { CUtensorMap m[25]; };

__device__ __forceinline__ void sample_pos(
    float r00, float r01, float r02,
    float r10, float r11, float r12,
    float r20, float r21, float r22,
    int x, int y, int z,
    float& fx, float& fy, float& fz)
{
    const float sc = 2.0f / 63.0f;
    float bx = fmaf((float)x, sc, -1.0f);
    float by = fmaf((float)y, sc, -1.0f);
    float bz = fmaf((float)z, sc, -1.0f);
    float gx = fmaf(r00, bx, fmaf(r10, by, r20 * bz));
    float gy = fmaf(r01, bx, fmaf(r11, by, r21 * bz));
    float gz = fmaf(r02, bx, fmaf(r12, by, r22 * bz));
    fx = fmaf(gx, 32.0f, 31.5f);
    fy = fmaf(gy, 32.0f, 31.5f);
    fz = fmaf(gz, 32.0f, 31.5f);
}

#define MBAR_WAIT(bar, par) do {                                              \
    unsigned _done;                                                           \
    asm volatile("{\n\t.reg .pred p;\n\t"                                     \
        "mbarrier.try_wait.parity.acquire.cta.shared::cta.b64 p, [%1], %2;\n\t"\
        "selp.b32 %0, 1, 0, p;\n\t}"                                          \
        : "=r"(_done) : "r"(bar), "r"(par) : "memory");                       \
    if (!_done) {                                                             \
        asm volatile("{\n\t.reg .pred P1;\n\t"                                \
            "WL_%=:\n\t"                                                      \
            "mbarrier.try_wait.parity.acquire.cta.shared::cta.b64 P1, [%0], %1, 0x989680;\n\t" \
            "@P1 bra.uni WD_%=;\n\t"                                          \
            "bra.uni WL_%=;\n\t"                                              \
            "WD_%=:\n\t}"                                                     \
            :: "r"(bar), "r"(par) : "memory");                                \
    }                                                                         \
} while (0)

__global__ __launch_bounds__(NTHR, 1)
void volrot_tma(const __grid_constant__ Maps maps,
                const float* __restrict__ rot,
                float* __restrict__ out,
                int culled)
{
    extern __shared__ float smemf[];
    __shared__ __align__(16) unsigned long long mbar[2];

    int tid = threadIdx.x;
    int blk = blockIdx.x;
    int b = blk >> 6;                 // 64 tiles per batch
    int t = blk & 63;
    int oz = (t >> 4) * TT;
    int oy = ((t >> 2) & 3) * TT;
    int ox = (t & 3) * TT;

    unsigned su_raw = (unsigned)__cvta_generic_to_shared(smemf);
    unsigned su = (su_raw + 1023u) & ~1023u;    // 1024B-aligned windows
    const char* wbase = (const char*)smemf + (su - su_raw);
    unsigned bar0 = (unsigned)__cvta_generic_to_shared(&mbar[0]);

    const float* R = rot + b * 9;
    float r00 = __ldg(R+0), r01 = __ldg(R+1), r02 = __ldg(R+2);
    float r10 = __ldg(R+3), r11 = __ldg(R+4), r12 = __ldg(R+5);
    float r20 = __ldg(R+6), r21 = __ldg(R+7), r22 = __ldg(R+8);

    // min/max sample coords over the 8 tile corners (affine => hull)
    float mnx = 1e30f, mny = 1e30f, mnz = 1e30f;
    float mxy = -1e30f, mxz = -1e30f;
    #pragma unroll
    for (int k = 0; k < 8; k++) {
        int cx = ox + ((k & 1) ? TT - 1 : 0);
        int cy = oy + ((k & 2) ? TT - 1 : 0);
        int cz = oz + ((k & 4) ? TT - 1 : 0);
        float fx, fy, fz;
        sample_pos(r00,r01,r02,r10,r11,r12,r20,r21,r22, cx, cy, cz, fx, fy, fz);
        mnx = fminf(mnx, fx); mny = fminf(mny, fy); mnz = fminf(mnz, fz);
        mxy = fmaxf(mxy, fy); mxz = fmaxf(mxz, fz);
    }
    int bax = ((int)floorf(mnx)) & ~3;   // 16B-aligned inner-dim start
    int bay = (int)floorf(mny);
    int baz = (int)floorf(mnz);

    // smallest sufficient box (or forced max when culled==0)
    int needY = ((int)floorf(mxy)) + 2 - bay;     // <= 29 guaranteed
    int needZ = ((int)floorf(mxz)) + 2 - baz;
    int iy = min(max(0, (needY - 20) >> 1), 4);
    int iz = min(max(0, (needZ - 20) >> 1), 4);
    if (!culled) { iy = 4; iz = 4; }
    int WY = 21 + 2 * iy;
    int WZ = 21 + 2 * iz;
    const CUtensorMap* tmap = &maps.m[iy * 5 + iz];
    unsigned txbytes = (unsigned)(WY * WZ * 128);

    // per-sample channel-invariant state (zero-fill OOB => no validity masks)
    unsigned pk[SPT];
    float ex0[SPT], ex1[SPT], wp0[SPT], wp1[SPT], wp2[SPT], wp3[SPT];
    unsigned obyte0 = 0;

    #pragma unroll
    for (int s = 0; s < SPT; s++) {
        int v = tid + s * NTHR;
        int lx = v & 15, ly = (v >> 4) & 15, lz = v >> 8;
        int x = ox + lx, y = oy + ly, z = oz + lz;
        float fx, fy, fz;
        sample_pos(r00,r01,r02,r10,r11,r12,r20,r21,r22, x, y, z, fx, fy, fz);
        float x0f = floorf(fx), y0f = floorf(fy), z0f = floorf(fz);
        float tx = fx - x0f, ty = fy - y0f, tz = fz - z0f;
        int x0 = (int)x0f, y0 = (int)y0f, z0 = (int)z0f;

        ex0[s] = 1.0f - tx;  ex1[s] = tx;
        wp0[s] = (1.0f - ty) * (1.0f - tz);
        wp1[s] = ty * (1.0f - tz);
        wp2[s] = (1.0f - ty) * tz;
        wp3[s] = ty * tz;

        int wx0 = min(max(x0 - bax, 0), 30);
        int wy0 = min(max(y0 - bay, 0), WY - 2);
        int wz0 = min(max(z0 - baz, 0), WZ - 2);
        unsigned rowid = (unsigned)(wz0 * WY + wy0);        // <= 810
        unsigned ca0 = (unsigned)((((wx0    ) >> 2) << 4) | (((wx0    ) & 3) << 2));
        unsigned ca1 = (unsigned)((((wx0 + 1) >> 2) << 4) | (((wx0 + 1) & 3) << 2));
        pk[s] = rowid | (ca0 << 10) | (ca1 << 18);
        if (s == 0) obyte0 = (unsigned)((((z * SB) + y) * SB + x) * 4);
    }

    if (tid == 0) {
        asm volatile("mbarrier.init.shared.b64 [%0], 1;" :: "r"(bar0)     : "memory");
        asm volatile("mbarrier.init.shared.b64 [%0], 1;" :: "r"(bar0 + 8) : "memory");
    }
    __syncthreads();

    int wcoord = b * CB;
    if (tid == 0) {
        #pragma unroll
        for (int c = 0; c < 2; c++) {
            unsigned bar = bar0 + 8u * (unsigned)c;
            asm volatile("mbarrier.arrive.expect_tx.shared.b64 _, [%0], %1;"
                :: "r"(bar), "r"(txbytes) : "memory");
            asm volatile(
                "cp.async.bulk.tensor.4d.shared::cta.global.tile.mbarrier::complete_tx::bytes "
                "[%0], [%1, {%2, %3, %4, %5}], [%6];"
                :: "r"(su + (unsigned)c * (unsigned)WIN_STRIDE), "l"(tmap),
                   "r"(bax), "r"(bay), "r"(baz), "r"(wcoord + c), "r"(bar)
                : "memory");
        }
    }

    char* dstb = (char*)out + (size_t)b * CB * S3 * 4;

    #pragma unroll 1
    for (int c = 0; c < CB; c++) {
        unsigned bar = bar0 + 8u * (unsigned)(c & 1);
        MBAR_WAIT(bar, (c >> 1) & 1);

        const char* wb = wbase + (unsigned)(c & 1) * (unsigned)WIN_STRIDE;
        char* dc = dstb + (size_t)c * S3 * 4 + obyte0;
        #pragma unroll
        for (int s = 0; s < SPT; s++) {
            unsigned p = pk[s];
            unsigned rowid = p & 1023u;
            unsigned ca0 = (p >> 10) & 0xFFu;
            unsigned ca1 = (p >> 18) & 0xFFu;

            unsigned rk0 = rowid * 128 + ((rowid & 7) << 4);
            unsigned rr1 = rowid + 1;
            unsigned rk1 = rr1 * 128 + ((rr1 & 7) << 4);
            unsigned rr2 = rowid + (unsigned)WY;
            unsigned rk2 = rr2 * 128 + ((rr2 & 7) << 4);
            unsigned rr3 = rr2 + 1;
            unsigned rk3 = rr3 * 128 + ((rr3 & 7) << 4);

            float v00 = *(const float*)(wb + (rk0 ^ ca0));
            float v01 = *(const float*)(wb + (rk0 ^ ca1));
            float v10 = *(const float*)(wb + (rk1 ^ ca0));
            float v11 = *(const float*)(wb + (rk1 ^ ca1));
            float v20 = *(const float*)(wb + (rk2 ^ ca0));
            float v21 = *(const float*)(wb + (rk2 ^ ca1));
            float v30 = *(const float*)(wb + (rk3 ^ ca0));
            float v31 = *(const float*)(wb + (rk3 ^ ca1));

            float s0 = fmaf(ex0[s], v00, ex1[s] * v01);
            float s1 = fmaf(ex0[s], v10, ex1[s] * v11);
            float s2 = fmaf(ex0[s], v20, ex1[s] * v21);
            float s3 = fmaf(ex0[s], v30, ex1[s] * v31);
            float acc = wp0[s] * s0;
            acc = fmaf(wp1[s], s1, acc);
            acc = fmaf(wp2[s], s2, acc);
            acc = fmaf(wp3[s], s3, acc);
            *(float*)(dc + (unsigned)(s * 65536)) = acc;   // lz += 4 per s
        }

        __syncthreads();   // buffer (c&1) fully consumed before refill
        if (c + 2 < CB && tid == 0) {
            asm volatile("mbarrier.arrive.expect_tx.shared.b64 _, [%0], %1;"
                :: "r"(bar), "r"(txbytes) : "memory");
            asm volatile(
                "cp.async.bulk.tensor.4d.shared::cta.global.tile.mbarrier::complete_tx::bytes "
                "[%0], [%1, {%2, %3, %4, %5}], [%6];"
                :: "r"(su + (unsigned)(c & 1) * (unsigned)WIN_STRIDE), "l"(tmap),
                   "r"(bax), "r"(bay), "r"(baz), "r"(wcoord + c + 2), "r"(bar)
                : "memory");
        }
    }
}

// ================================ host =====================================

extern "C" void kernel_launch(void* const* d_in, const int* in_sizes, int n_in,
                              void* d_out, int out_size)
{
    const float* vol = (const float*)d_in[0];   // [8,16,64,64,64] f32
    const float* rot = (const float*)d_in[1];   // [8,3,3] f32
    float* out = (float*)d_out;

    typedef CUresult (*EncodeFn)(
        CUtensorMap*, CUtensorMapDataType, cuuint32_t, void*,
        const cuuint64_t*, const cuuint64_t*, const cuuint32_t*,
        const cuuint32_t*, CUtensorMapInterleave, CUtensorMapSwizzle,
        CUtensorMapL2promotion, CUtensorMapFloatOOBfill);
    EncodeFn encode = nullptr;
#if CUDART_VERSION >= 12050
    cudaDriverEntryPointQueryResult qr;
    if (cudaGetDriverEntryPointByVersion("cuTensorMapEncodeTiled",
            (void**)&encode, 12000, cudaEnableDefault, &qr) != cudaSuccess ||
        qr != cudaDriverEntryPointSuccess)
        encode = nullptr;
#else
    if (cudaGetDriverEntryPoint("cuTensorMapEncodeTiled",
            (void**)&encode, cudaEnableDefault) != cudaSuccess)
        encode = nullptr;
#endif

    static Maps maps;
    cuuint64_t dims[4]    = {64, 64, 64, 128};
    cuuint64_t strides[3] = {64ull * 4, 64ull * 64 * 4, 64ull * 64 * 64 * 4};
    cuuint32_t est[4]     = {1, 1, 1, 1};

    int all_ok = (encode != nullptr);
    for (int iy = 0; iy < 5 && all_ok; iy++) {
        for (int iz = 0; iz < 5 && all_ok; iz++) {
            cuuint32_t box[4] = {32, (cuuint32_t)(21 + 2 * iy),
                                     (cuuint32_t)(21 + 2 * iz), 1};
            CUtensorMap tmp;
            __builtin_memset(&tmp, 0, sizeof(tmp));
            if (encode(&tmp, CU_TENSOR_MAP_DATA_TYPE_FLOAT32, 4,
                       (void*)vol, dims, strides, box, est,
                       CU_TENSOR_MAP_INTERLEAVE_NONE,
                       CU_TENSOR_MAP_SWIZZLE_128B,
                       CU_TENSOR_MAP_L2_PROMOTION_L2_128B,
                       CU_TENSOR_MAP_FLOAT_OOB_FILL_NONE) == CUDA_SUCCESS)
                maps.m[iy * 5 + iz] = tmp;
            else
                all_ok = 0;
        }
    }
    if (!all_ok && encode) {
        // force every slot to the max box; kernel runs with culled=0 and only
        // ever dereferences slot (4,4), with txbytes = 29*29*128 (consistent).
        CUtensorMap big;
        __builtin_memset(&big, 0, sizeof(big));
        cuuint32_t box[4] = {32, WMAX, WMAX, 1};
        encode(&big, CU_TENSOR_MAP_DATA_TYPE_FLOAT32, 4, (void*)vol,
               dims, strides, box, est,
               CU_TENSOR_MAP_INTERLEAVE_NONE, CU_TENSOR_MAP_SWIZZLE_128B,
               CU_TENSOR_MAP_L2_PROMOTION_L2_128B,
               CU_TENSOR_MAP_FLOAT_OOB_FILL_NONE);
        for (int i = 0; i < 25; i++) maps.m[i] = big;
    }

    cudaFuncSetAttribute(volrot_tma,
                         cudaFuncAttributeMaxDynamicSharedMemorySize, SMEM_BYTES);

    volrot_tma<<<8 * 64, NTHR, SMEM_BYTES>>>(maps, rot, out, all_ok);
}